// round 12
// baseline (speedup 1.0000x reference)
#include <cuda_runtime.h>
#include <cuda_bf16.h>

// I_MLP_7206955123212 — B=2^21 independent 10-step tiny-MLP rollouts.
// R10 winner (RPT=3, smem weights, zero spill, 150.1us) + sqrt de-MUFU:
// the two err-norm sqrt sites use integer-magic rsqrt (ALU) + 2 Newton
// steps (FMA pipe), removing 2 of 24 MUFU sites per row-step. MUFU is the
// measured wall (16 SFU/SM -> 135us floor at 24 sites; 88% saturated).
// NO memory-indexed tables (R11 showed indexed LDS bank-conflicts cost more
// than the MUFU they save).

__device__ __forceinline__ float tanh_fast(float x) {
    float y; asm("tanh.approx.f32 %0,%1;" : "=f"(y) : "f"(x)); return y;
}
// sqrt with no MUFU: magic rsqrt seed (ALU pipe) + 2 Newton iters (FMA pipe).
// +1e-30 guards x==0 exactly (both pred nets saturated identically) which
// would otherwise hit 0*inf=NaN in the Newton step. rel err ~5e-6.
__device__ __forceinline__ float sqrt_nomufu(float x) {
    x = x + 1e-30f;
    int i = __float_as_int(x);
    i = 0x5f3759df - (i >> 1);
    float y = __int_as_float(i);
    const float h = 0.5f * x;
    y = y * fmaf(-h, y * y, 1.5f);
    y = y * fmaf(-h, y * y, 1.5f);
    return x * y;
}

// g_w layout (floats):
//  [0..19]    pred: Wf00,Wf01,Wf10,Wf11, Wh00,Wh01,Wh10,Wh11,
//                   WfS(4), WhS(4), Bf0,Bf1,Bh0,Bh1
//  [20..51]   rc1_w (j*4+k)       [52..59]   rc1_b
//  [60..123]  rc2_w (j*8+k)       [124..131] rc2_b
//  [132..147] rc3_w (r*8+k)       [148..149] rc3_b
__device__ float g_w[160];

__global__ void prep_kernel(const float* __restrict__ fc1_w, const float* __restrict__ fc1_b,
                            const float* __restrict__ fc2_w, const float* __restrict__ fc2_b,
                            const float* __restrict__ rc1_w, const float* __restrict__ rc1_b,
                            const float* __restrict__ rc2_w, const float* __restrict__ rc2_b,
                            const float* __restrict__ rc3_w, const float* __restrict__ rc3_b,
                            const float* __restrict__ hf1_w, const float* __restrict__ hf1_b,
                            const float* __restrict__ hf2_w, const float* __restrict__ hf2_b)
{
    if (threadIdx.x != 0 || blockIdx.x != 0) return;

    // Fuse fc2@fc1 and hf2@hf1 (no activation between) into 2x4 affines.
    float Wf[2][4], Wh[2][4], Bf[2], Bh[2];
    for (int r = 0; r < 2; ++r) {
        for (int k = 0; k < 4; ++k) {
            float af = 0.f, ah = 0.f;
            for (int j = 0; j < 4; ++j) {
                af = fmaf(fc2_w[r * 4 + j], fc1_w[j * 4 + k], af);
                ah = fmaf(hf2_w[r * 4 + j], hf1_w[j * 4 + k], ah);
            }
            Wf[r][k] = af; Wh[r][k] = ah;
        }
        float bf = fc2_b[r], bh = hf2_b[r];
        for (int j = 0; j < 4; ++j) {
            bf = fmaf(fc2_w[r * 4 + j], fc1_b[j], bf);
            bh = fmaf(hf2_w[r * 4 + j], hf1_b[j], bh);
        }
        Bf[r] = bf; Bh[r] = bh;
    }
    g_w[0] = Wf[0][0]; g_w[1] = Wf[0][1]; g_w[2] = Wf[1][0]; g_w[3] = Wf[1][1];
    g_w[4] = Wh[0][0]; g_w[5] = Wh[0][1]; g_w[6] = Wh[1][0]; g_w[7] = Wh[1][1];
    g_w[8]  = Wf[0][2]; g_w[9]  = Wf[0][3]; g_w[10] = Wf[1][2]; g_w[11] = Wf[1][3];
    g_w[12] = Wh[0][2]; g_w[13] = Wh[0][3]; g_w[14] = Wh[1][2]; g_w[15] = Wh[1][3];
    g_w[16] = Bf[0]; g_w[17] = Bf[1]; g_w[18] = Bh[0]; g_w[19] = Bh[1];

    for (int i = 0; i < 32; ++i) g_w[20 + i]  = rc1_w[i];
    for (int i = 0; i < 8;  ++i) g_w[52 + i]  = rc1_b[i];
    for (int i = 0; i < 64; ++i) g_w[60 + i]  = rc2_w[i];
    for (int i = 0; i < 8;  ++i) g_w[124 + i] = rc2_b[i];
    for (int i = 0; i < 16; ++i) g_w[132 + i] = rc3_w[i];
    for (int i = 0; i < 2;  ++i) g_w[148 + i] = rc3_b[i];
}

#define RPT 3

__global__ void __launch_bounds__(128, 4)
rollout_kernel(const float* __restrict__ s_star, const float* __restrict__ s0,
               float* __restrict__ out, int B)
{
    // smem: s_pred[20], then rc blocks in s_w (16B aligned):
    //  rc1w @0, rc1b @32, rc2w @40, rc2b @104, rc3w @112, rc3b @128
    __shared__ float s_pred[20];
    __shared__ __align__(16) float s_w[132];
    for (int i = threadIdx.x; i < 150; i += blockDim.x) {
        if (i < 20) s_pred[i] = g_w[i];
        else        s_w[i - 20] = g_w[i];
    }
    __syncthreads();

    const float4* __restrict__ s4_rc1 = reinterpret_cast<const float4*>(s_w + 0);
    const float*  __restrict__ s_rc1b = s_w + 32;
    const float4* __restrict__ s4_rc2 = reinterpret_cast<const float4*>(s_w + 40);
    const float*  __restrict__ s_rc2b = s_w + 104;
    const float4* __restrict__ s4_rc3 = reinterpret_cast<const float4*>(s_w + 112);
    const float*  __restrict__ s_rc3b = s_w + 128;

    const int base = (blockIdx.x * blockDim.x + threadIdx.x) * RPT;
    if (base >= B) return;

    const float Wf00 = s_pred[0], Wf01 = s_pred[1], Wf10 = s_pred[2], Wf11 = s_pred[3];
    const float Wh00 = s_pred[4], Wh01 = s_pred[5], Wh10 = s_pred[6], Wh11 = s_pred[7];

    float sx[RPT], sy[RPT], ssx[RPT], ssy[RPT], err[RPT];
    float Cf0[RPT], Cf1[RPT], Ch0[RPT], Ch1[RPT];
    #pragma unroll
    for (int r = 0; r < RPT; ++r) {
        const int i = (base + r < B) ? base + r : B - 1;
        const float2 ssv = reinterpret_cast<const float2*>(s_star)[i];
        const float2 s0v = reinterpret_cast<const float2*>(s0)[i];
        ssx[r] = ssv.x; ssy[r] = ssv.y;
        sx[r] = s0v.x;  sy[r] = s0v.y;  err[r] = 0.f;
        Cf0[r] = fmaf(s_pred[8],  ssv.x, fmaf(s_pred[9],  ssv.y, s_pred[16]));
        Cf1[r] = fmaf(s_pred[10], ssv.x, fmaf(s_pred[11], ssv.y, s_pred[17]));
        Ch0[r] = fmaf(s_pred[12], ssv.x, fmaf(s_pred[13], ssv.y, s_pred[18]));
        Ch1[r] = fmaf(s_pred[14], ssv.x, fmaf(s_pred[15], ssv.y, s_pred[19]));
    }

    // Step loop NOT unrolled: keeps smem weight loads inside the loop body
    // (hoisting them into long-lived registers is what causes spills).
    #pragma unroll 1
    for (int t = 0; t < 10; ++t) {
        float ah0[RPT], ah1[RPT];
        #pragma unroll
        for (int r = 0; r < RPT; ++r) {
            // prediction nets (register weights)
            ah0[r] = tanh_fast(fmaf(Wf00, sx[r], fmaf(Wf01, sy[r], Cf0[r])));
            ah1[r] = tanh_fast(fmaf(Wf10, sx[r], fmaf(Wf11, sy[r], Cf1[r])));
            const float ag0 = tanh_fast(fmaf(Wh00, sx[r], fmaf(Wh01, sy[r], Ch0[r])));
            const float ag1 = tanh_fast(fmaf(Wh10, sx[r], fmaf(Wh11, sy[r], Ch1[r])));
            // detached-pred err term consumed immediately (kills ag live range)
            const float d0 = ah0[r] - ag0, d1 = ah1[r] - ag1;
            float e = err[r];
            e += sqrt_nomufu(fmaf(d0, d0, d1 * d1));
            // ah-only err terms here too (ah stays live only through rc1)
            e += tanh_fast(ah0[r]) + tanh_fast(ah1[r]);
            e += sqrt_nomufu(fmaf(ah0[r], ah0[r], ah1[r] * ah1[r]));
            err[r] = e;
        }

        // rc1: [s, ah] -> 8  (weights broadcast from smem, shared by all rows)
        float h1[RPT][8];
        #pragma unroll
        for (int j = 0; j < 8; ++j) {
            const float4 w = s4_rc1[j];
            const float  b = s_rc1b[j];
            #pragma unroll
            for (int r = 0; r < RPT; ++r)
                h1[r][j] = tanh_fast(fmaf(w.x, sx[r],
                                     fmaf(w.y, sy[r],
                                     fmaf(w.z, ah0[r],
                                     fmaf(w.w, ah1[r], b)))));
        }

        // rc2: 8 -> 8
        float h2[RPT][8];
        #pragma unroll
        for (int j = 0; j < 8; ++j) {
            const float4 wa = s4_rc2[2 * j];
            const float4 wb = s4_rc2[2 * j + 1];
            const float  b  = s_rc2b[j];
            #pragma unroll
            for (int r = 0; r < RPT; ++r) {
                float a = fmaf(wa.x, h1[r][0], fmaf(wa.y, h1[r][1],
                          fmaf(wa.z, h1[r][2], fmaf(wa.w, h1[r][3], b))));
                a = fmaf(wb.x, h1[r][4], fmaf(wb.y, h1[r][5],
                    fmaf(wb.z, h1[r][6], fmaf(wb.w, h1[r][7], a))));
                h2[r][j] = tanh_fast(a);
            }
        }

        // rc3: 8 -> 2, state update, tracking error
        {
            const float4 wa0 = s4_rc3[0], wa1 = s4_rc3[1];
            const float4 wb0 = s4_rc3[2], wb1 = s4_rc3[3];
            const float  b30 = s_rc3b[0], b31 = s_rc3b[1];
            #pragma unroll
            for (int r = 0; r < RPT; ++r) {
                float ar0 = fmaf(wa0.x, h2[r][0], fmaf(wa0.y, h2[r][1],
                            fmaf(wa0.z, h2[r][2], fmaf(wa0.w, h2[r][3], b30))));
                ar0 = fmaf(wa1.x, h2[r][4], fmaf(wa1.y, h2[r][5],
                      fmaf(wa1.z, h2[r][6], fmaf(wa1.w, h2[r][7], ar0))));
                float ar1 = fmaf(wb0.x, h2[r][0], fmaf(wb0.y, h2[r][1],
                            fmaf(wb0.z, h2[r][2], fmaf(wb0.w, h2[r][3], b31))));
                ar1 = fmaf(wb1.x, h2[r][4], fmaf(wb1.y, h2[r][5],
                      fmaf(wb1.z, h2[r][6], fmaf(wb1.w, h2[r][7], ar1))));
                sx[r] = fmaf(0.1f, ar0, sx[r]);
                sy[r] = fmaf(0.1f, ar1, sy[r]);

                const float dx = sx[r] - ssx[r], dy = sy[r] - ssy[r];
                err[r] += fmaf(dx, dx, dy * dy);
            }
        }
    }

    #pragma unroll
    for (int r = 0; r < RPT; ++r)
        if (base + r < B) out[base + r] = err[r];
}

extern "C" void kernel_launch(void* const* d_in, const int* in_sizes, int n_in,
                              void* d_out, int out_size)
{
    const float* s_star = (const float*)d_in[0];
    const float* s0     = (const float*)d_in[1];
    const float* fc1_w  = (const float*)d_in[2];
    const float* fc1_b  = (const float*)d_in[3];
    const float* fc2_w  = (const float*)d_in[4];
    const float* fc2_b  = (const float*)d_in[5];
    const float* rc1_w  = (const float*)d_in[6];
    const float* rc1_b  = (const float*)d_in[7];
    const float* rc2_w  = (const float*)d_in[8];
    const float* rc2_b  = (const float*)d_in[9];
    const float* rc3_w  = (const float*)d_in[10];
    const float* rc3_b  = (const float*)d_in[11];
    const float* hf1_w  = (const float*)d_in[12];
    const float* hf1_b  = (const float*)d_in[13];
    const float* hf2_w  = (const float*)d_in[14];
    const float* hf2_b  = (const float*)d_in[15];
    float* out = (float*)d_out;

    const int B = out_size;

    prep_kernel<<<1, 1>>>(fc1_w, fc1_b, fc2_w, fc2_b,
                          rc1_w, rc1_b, rc2_w, rc2_b, rc3_w, rc3_b,
                          hf1_w, hf1_b, hf2_w, hf2_b);

    const int threads = 128;
    const int rows_per_block = threads * RPT;
    const int blocks = (B + rows_per_block - 1) / rows_per_block;
    rollout_kernel<<<blocks, threads>>>(s_star, s0, out, B);
}

// round 14
// speedup vs baseline: 1.0057x; 1.0057x over previous
#include <cuda_runtime.h>
#include <cuda_bf16.h>

// I_MLP_7206955123212 — B=2^21 independent 10-step tiny-MLP rollouts.
// Exact R10 math (best: 150.1us — RPT=3, smem weights, MUFU tanh/sqrt,
// zero spill) + step-loop unroll 2: overlap the tail of step t (rc3/err
// serial chain) with the head of step t+1 (rc1 LDS + pred nets) for issue
// efficiency. Evidence: R11/R12 showed MUFU->instr trades lose; the kernel
// is issue/latency-bound, so the only free lever is scheduling overlap.

__device__ __forceinline__ float tanh_fast(float x) {
    float y; asm("tanh.approx.f32 %0,%1;" : "=f"(y) : "f"(x)); return y;
}
__device__ __forceinline__ float sqrt_fast(float x) {
    float y; asm("sqrt.approx.f32 %0,%1;" : "=f"(y) : "f"(x)); return y;
}

// g_w layout (floats):
//  [0..19]    pred: Wf00,Wf01,Wf10,Wf11, Wh00,Wh01,Wh10,Wh11,
//                   WfS(4), WhS(4), Bf0,Bf1,Bh0,Bh1
//  [20..51]   rc1_w (j*4+k)       [52..59]   rc1_b
//  [60..123]  rc2_w (j*8+k)       [124..131] rc2_b
//  [132..147] rc3_w (r*8+k)       [148..149] rc3_b
__device__ float g_w[160];

__global__ void prep_kernel(const float* __restrict__ fc1_w, const float* __restrict__ fc1_b,
                            const float* __restrict__ fc2_w, const float* __restrict__ fc2_b,
                            const float* __restrict__ rc1_w, const float* __restrict__ rc1_b,
                            const float* __restrict__ rc2_w, const float* __restrict__ rc2_b,
                            const float* __restrict__ rc3_w, const float* __restrict__ rc3_b,
                            const float* __restrict__ hf1_w, const float* __restrict__ hf1_b,
                            const float* __restrict__ hf2_w, const float* __restrict__ hf2_b)
{
    if (threadIdx.x != 0 || blockIdx.x != 0) return;

    // Fuse fc2@fc1 and hf2@hf1 (no activation between) into 2x4 affines.
    float Wf[2][4], Wh[2][4], Bf[2], Bh[2];
    for (int r = 0; r < 2; ++r) {
        for (int k = 0; k < 4; ++k) {
            float af = 0.f, ah = 0.f;
            for (int j = 0; j < 4; ++j) {
                af = fmaf(fc2_w[r * 4 + j], fc1_w[j * 4 + k], af);
                ah = fmaf(hf2_w[r * 4 + j], hf1_w[j * 4 + k], ah);
            }
            Wf[r][k] = af; Wh[r][k] = ah;
        }
        float bf = fc2_b[r], bh = hf2_b[r];
        for (int j = 0; j < 4; ++j) {
            bf = fmaf(fc2_w[r * 4 + j], fc1_b[j], bf);
            bh = fmaf(hf2_w[r * 4 + j], hf1_b[j], bh);
        }
        Bf[r] = bf; Bh[r] = bh;
    }
    g_w[0] = Wf[0][0]; g_w[1] = Wf[0][1]; g_w[2] = Wf[1][0]; g_w[3] = Wf[1][1];
    g_w[4] = Wh[0][0]; g_w[5] = Wh[0][1]; g_w[6] = Wh[1][0]; g_w[7] = Wh[1][1];
    g_w[8]  = Wf[0][2]; g_w[9]  = Wf[0][3]; g_w[10] = Wf[1][2]; g_w[11] = Wf[1][3];
    g_w[12] = Wh[0][2]; g_w[13] = Wh[0][3]; g_w[14] = Wh[1][2]; g_w[15] = Wh[1][3];
    g_w[16] = Bf[0]; g_w[17] = Bf[1]; g_w[18] = Bh[0]; g_w[19] = Bh[1];

    for (int i = 0; i < 32; ++i) g_w[20 + i]  = rc1_w[i];
    for (int i = 0; i < 8;  ++i) g_w[52 + i]  = rc1_b[i];
    for (int i = 0; i < 64; ++i) g_w[60 + i]  = rc2_w[i];
    for (int i = 0; i < 8;  ++i) g_w[124 + i] = rc2_b[i];
    for (int i = 0; i < 16; ++i) g_w[132 + i] = rc3_w[i];
    for (int i = 0; i < 2;  ++i) g_w[148 + i] = rc3_b[i];
}

#define RPT 3

__global__ void __launch_bounds__(128, 4)
rollout_kernel(const float* __restrict__ s_star, const float* __restrict__ s0,
               float* __restrict__ out, int B)
{
    // smem: s_pred[20], then rc blocks in s_w (16B aligned):
    //  rc1w @0, rc1b @32, rc2w @40, rc2b @104, rc3w @112, rc3b @128
    __shared__ float s_pred[20];
    __shared__ __align__(16) float s_w[132];
    for (int i = threadIdx.x; i < 150; i += blockDim.x) {
        if (i < 20) s_pred[i] = g_w[i];
        else        s_w[i - 20] = g_w[i];
    }
    __syncthreads();

    const float4* __restrict__ s4_rc1 = reinterpret_cast<const float4*>(s_w + 0);
    const float*  __restrict__ s_rc1b = s_w + 32;
    const float4* __restrict__ s4_rc2 = reinterpret_cast<const float4*>(s_w + 40);
    const float*  __restrict__ s_rc2b = s_w + 104;
    const float4* __restrict__ s4_rc3 = reinterpret_cast<const float4*>(s_w + 112);
    const float*  __restrict__ s_rc3b = s_w + 128;

    const int base = (blockIdx.x * blockDim.x + threadIdx.x) * RPT;
    if (base >= B) return;

    const float Wf00 = s_pred[0], Wf01 = s_pred[1], Wf10 = s_pred[2], Wf11 = s_pred[3];
    const float Wh00 = s_pred[4], Wh01 = s_pred[5], Wh10 = s_pred[6], Wh11 = s_pred[7];

    float sx[RPT], sy[RPT], ssx[RPT], ssy[RPT], err[RPT];
    float Cf0[RPT], Cf1[RPT], Ch0[RPT], Ch1[RPT];
    #pragma unroll
    for (int r = 0; r < RPT; ++r) {
        const int i = (base + r < B) ? base + r : B - 1;
        const float2 ssv = reinterpret_cast<const float2*>(s_star)[i];
        const float2 s0v = reinterpret_cast<const float2*>(s0)[i];
        ssx[r] = ssv.x; ssy[r] = ssv.y;
        sx[r] = s0v.x;  sy[r] = s0v.y;  err[r] = 0.f;
        Cf0[r] = fmaf(s_pred[8],  ssv.x, fmaf(s_pred[9],  ssv.y, s_pred[16]));
        Cf1[r] = fmaf(s_pred[10], ssv.x, fmaf(s_pred[11], ssv.y, s_pred[17]));
        Ch0[r] = fmaf(s_pred[12], ssv.x, fmaf(s_pred[13], ssv.y, s_pred[18]));
        Ch1[r] = fmaf(s_pred[14], ssv.x, fmaf(s_pred[15], ssv.y, s_pred[19]));
    }

    // unroll 2: pairs of steps are interleavable by the scheduler — the tail
    // of step t (rc3 + err chain) overlaps the head of t+1 (rc1 LDS, pred).
    // Weight LDS stays in-body (full unroll/hoist is the known spill path).
    #pragma unroll 2
    for (int t = 0; t < 10; ++t) {
        float ah0[RPT], ah1[RPT];
        #pragma unroll
        for (int r = 0; r < RPT; ++r) {
            // prediction nets (register weights)
            ah0[r] = tanh_fast(fmaf(Wf00, sx[r], fmaf(Wf01, sy[r], Cf0[r])));
            ah1[r] = tanh_fast(fmaf(Wf10, sx[r], fmaf(Wf11, sy[r], Cf1[r])));
            const float ag0 = tanh_fast(fmaf(Wh00, sx[r], fmaf(Wh01, sy[r], Ch0[r])));
            const float ag1 = tanh_fast(fmaf(Wh10, sx[r], fmaf(Wh11, sy[r], Ch1[r])));
            // detached-pred err term consumed immediately (kills ag live range)
            const float d0 = ah0[r] - ag0, d1 = ah1[r] - ag1;
            float e = err[r];
            e += sqrt_fast(fmaf(d0, d0, d1 * d1));
            // ah-only err terms here too (ah stays live only through rc1)
            e += tanh_fast(ah0[r]) + tanh_fast(ah1[r]);
            e += sqrt_fast(fmaf(ah0[r], ah0[r], ah1[r] * ah1[r]));
            err[r] = e;
        }

        // rc1: [s, ah] -> 8  (weights broadcast from smem, shared by all rows)
        float h1[RPT][8];
        #pragma unroll
        for (int j = 0; j < 8; ++j) {
            const float4 w = s4_rc1[j];
            const float  b = s_rc1b[j];
            #pragma unroll
            for (int r = 0; r < RPT; ++r)
                h1[r][j] = tanh_fast(fmaf(w.x, sx[r],
                                     fmaf(w.y, sy[r],
                                     fmaf(w.z, ah0[r],
                                     fmaf(w.w, ah1[r], b)))));
        }

        // rc2: 8 -> 8
        float h2[RPT][8];
        #pragma unroll
        for (int j = 0; j < 8; ++j) {
            const float4 wa = s4_rc2[2 * j];
            const float4 wb = s4_rc2[2 * j + 1];
            const float  b  = s_rc2b[j];
            #pragma unroll
            for (int r = 0; r < RPT; ++r) {
                float a = fmaf(wa.x, h1[r][0], fmaf(wa.y, h1[r][1],
                          fmaf(wa.z, h1[r][2], fmaf(wa.w, h1[r][3], b))));
                a = fmaf(wb.x, h1[r][4], fmaf(wb.y, h1[r][5],
                    fmaf(wb.z, h1[r][6], fmaf(wb.w, h1[r][7], a))));
                h2[r][j] = tanh_fast(a);
            }
        }

        // rc3: 8 -> 2, state update, tracking error
        {
            const float4 wa0 = s4_rc3[0], wa1 = s4_rc3[1];
            const float4 wb0 = s4_rc3[2], wb1 = s4_rc3[3];
            const float  b30 = s_rc3b[0], b31 = s_rc3b[1];
            #pragma unroll
            for (int r = 0; r < RPT; ++r) {
                float ar0 = fmaf(wa0.x, h2[r][0], fmaf(wa0.y, h2[r][1],
                            fmaf(wa0.z, h2[r][2], fmaf(wa0.w, h2[r][3], b30))));
                ar0 = fmaf(wa1.x, h2[r][4], fmaf(wa1.y, h2[r][5],
                      fmaf(wa1.z, h2[r][6], fmaf(wa1.w, h2[r][7], ar0))));
                float ar1 = fmaf(wb0.x, h2[r][0], fmaf(wb0.y, h2[r][1],
                            fmaf(wb0.z, h2[r][2], fmaf(wb0.w, h2[r][3], b31))));
                ar1 = fmaf(wb1.x, h2[r][4], fmaf(wb1.y, h2[r][5],
                      fmaf(wb1.z, h2[r][6], fmaf(wb1.w, h2[r][7], ar1))));
                sx[r] = fmaf(0.1f, ar0, sx[r]);
                sy[r] = fmaf(0.1f, ar1, sy[r]);

                const float dx = sx[r] - ssx[r], dy = sy[r] - ssy[r];
                err[r] += fmaf(dx, dx, dy * dy);
            }
        }
    }

    #pragma unroll
    for (int r = 0; r < RPT; ++r)
        if (base + r < B) out[base + r] = err[r];
}

extern "C" void kernel_launch(void* const* d_in, const int* in_sizes, int n_in,
                              void* d_out, int out_size)
{
    const float* s_star = (const float*)d_in[0];
    const float* s0     = (const float*)d_in[1];
    const float* fc1_w  = (const float*)d_in[2];
    const float* fc1_b  = (const float*)d_in[3];
    const float* fc2_w  = (const float*)d_in[4];
    const float* fc2_b  = (const float*)d_in[5];
    const float* rc1_w  = (const float*)d_in[6];
    const float* rc1_b  = (const float*)d_in[7];
    const float* rc2_w  = (const float*)d_in[8];
    const float* rc2_b  = (const float*)d_in[9];
    const float* rc3_w  = (const float*)d_in[10];
    const float* rc3_b  = (const float*)d_in[11];
    const float* hf1_w  = (const float*)d_in[12];
    const float* hf1_b  = (const float*)d_in[13];
    const float* hf2_w  = (const float*)d_in[14];
    const float* hf2_b  = (const float*)d_in[15];
    float* out = (float*)d_out;

    const int B = out_size;

    prep_kernel<<<1, 1>>>(fc1_w, fc1_b, fc2_w, fc2_b,
                          rc1_w, rc1_b, rc2_w, rc2_b, rc3_w, rc3_b,
                          hf1_w, hf1_b, hf2_w, hf2_b);

    const int threads = 128;
    const int rows_per_block = threads * RPT;
    const int blocks = (B + rows_per_block - 1) / rows_per_block;
    rollout_kernel<<<blocks, threads>>>(s_star, s0, out, B);
}

// round 16
// speedup vs baseline: 1.0554x; 1.0494x over previous
#include <cuda_runtime.h>
#include <cuda_bf16.h>

// I_MLP_7206955123212 — B=2^21 independent 10-step tiny-MLP rollouts.
// Hybrid scalar + tensor-core kernel:
//  - pred nets / err terms / state updates: lane-local fp32 (exact R10 math)
//  - rc1->rc2->rc3 dense chain: legacy mma.m16n8k8 tf32, 6 tiles x 3 MMAs
//    per warp-step (96 rows/warp, RPT=3), with the C->A fragment layout
//    mismatch absorbed into a precomputed k-permutation of the next layer's
//    B fragment (zero shuffles between layers; tanh elementwise on frags).
//  - entry/exit via small conflict-free smem transposes inside the warp.

__device__ __forceinline__ float tanh_fast(float x) {
    float y; asm("tanh.approx.f32 %0,%1;" : "=f"(y) : "f"(x)); return y;
}
__device__ __forceinline__ float sqrt_fast(float x) {
    float y; asm("sqrt.approx.f32 %0,%1;" : "=f"(y) : "f"(x)); return y;
}
__device__ __forceinline__ unsigned tf32_of(float x) {
    unsigned u; asm("cvt.rna.tf32.f32 %0, %1;" : "=r"(u) : "f"(x)); return u;
}
__device__ __forceinline__ void mma_tf32(
    float& d0, float& d1, float& d2, float& d3,
    unsigned a0, unsigned a1, unsigned a2, unsigned a3,
    unsigned b0, unsigned b1,
    float c0, float c1, float c2, float c3)
{
    asm("mma.sync.aligned.m16n8k8.row.col.f32.tf32.tf32.f32 "
        "{%0,%1,%2,%3}, {%4,%5,%6,%7}, {%8,%9}, {%10,%11,%12,%13};"
        : "=f"(d0), "=f"(d1), "=f"(d2), "=f"(d3)
        : "r"(a0), "r"(a1), "r"(a2), "r"(a3), "r"(b0), "r"(b1),
          "f"(c0), "f"(c1), "f"(c2), "f"(c3));
}

// g_w layout (floats):
//  [0..19]    pred: Wf00,Wf01,Wf10,Wf11, Wh00,Wh01,Wh10,Wh11,
//                   WfS(4), WhS(4), Bf0,Bf1,Bh0,Bh1
//  [20..51]   rc1_w (j*4+k)       [52..59]   rc1_b
//  [60..123]  rc2_w (j*8+k)       [124..131] rc2_b
//  [132..147] rc3_w (r*8+k)       [148..149] rc3_b
__device__ float g_w[160];

__global__ void prep_kernel(const float* __restrict__ fc1_w, const float* __restrict__ fc1_b,
                            const float* __restrict__ fc2_w, const float* __restrict__ fc2_b,
                            const float* __restrict__ rc1_w, const float* __restrict__ rc1_b,
                            const float* __restrict__ rc2_w, const float* __restrict__ rc2_b,
                            const float* __restrict__ rc3_w, const float* __restrict__ rc3_b,
                            const float* __restrict__ hf1_w, const float* __restrict__ hf1_b,
                            const float* __restrict__ hf2_w, const float* __restrict__ hf2_b)
{
    if (threadIdx.x != 0 || blockIdx.x != 0) return;

    float Wf[2][4], Wh[2][4], Bf[2], Bh[2];
    for (int r = 0; r < 2; ++r) {
        for (int k = 0; k < 4; ++k) {
            float af = 0.f, ah = 0.f;
            for (int j = 0; j < 4; ++j) {
                af = fmaf(fc2_w[r * 4 + j], fc1_w[j * 4 + k], af);
                ah = fmaf(hf2_w[r * 4 + j], hf1_w[j * 4 + k], ah);
            }
            Wf[r][k] = af; Wh[r][k] = ah;
        }
        float bf = fc2_b[r], bh = hf2_b[r];
        for (int j = 0; j < 4; ++j) {
            bf = fmaf(fc2_w[r * 4 + j], fc1_b[j], bf);
            bh = fmaf(hf2_w[r * 4 + j], hf1_b[j], bh);
        }
        Bf[r] = bf; Bh[r] = bh;
    }
    g_w[0] = Wf[0][0]; g_w[1] = Wf[0][1]; g_w[2] = Wf[1][0]; g_w[3] = Wf[1][1];
    g_w[4] = Wh[0][0]; g_w[5] = Wh[0][1]; g_w[6] = Wh[1][0]; g_w[7] = Wh[1][1];
    g_w[8]  = Wf[0][2]; g_w[9]  = Wf[0][3]; g_w[10] = Wf[1][2]; g_w[11] = Wf[1][3];
    g_w[12] = Wh[0][2]; g_w[13] = Wh[0][3]; g_w[14] = Wh[1][2]; g_w[15] = Wh[1][3];
    g_w[16] = Bf[0]; g_w[17] = Bf[1]; g_w[18] = Bh[0]; g_w[19] = Bh[1];

    for (int i = 0; i < 32; ++i) g_w[20 + i]  = rc1_w[i];
    for (int i = 0; i < 8;  ++i) g_w[52 + i]  = rc1_b[i];
    for (int i = 0; i < 64; ++i) g_w[60 + i]  = rc2_w[i];
    for (int i = 0; i < 8;  ++i) g_w[124 + i] = rc2_b[i];
    for (int i = 0; i < 16; ++i) g_w[132 + i] = rc3_w[i];
    for (int i = 0; i < 2;  ++i) g_w[148 + i] = rc3_b[i];
}

#define RPT 3
#define NTILE 6   // 96 rows/warp = 6 x m16

__global__ void __launch_bounds__(128, 4)
rollout_kernel(const float* __restrict__ s_star, const float* __restrict__ s0,
               float* __restrict__ out, int B)
{
    // s_pred: fused pred-net consts. s_w: rc weights (R10 offsets:
    // rc1w @0, rc1b @32, rc2w @40, rc2b @104, rc3w @112, rc3b @128).
    __shared__ float s_pred[20];
    __shared__ __align__(16) float s_w[132];
    // per-warp staging: x rows (4 floats/row) and ar rows (2 floats/row)
    __shared__ __align__(16) float x_sm[4][96 * 4];
    __shared__ __align__(16) float ar_sm[4][96 * 2];

    const int tid  = threadIdx.x;
    const int wid  = tid >> 5;
    const int lane = tid & 31;
    const int gid  = lane >> 2;   // groupID (0..7)
    const int tig  = lane & 3;    // threadID in group (0..3)

    for (int i = tid; i < 150; i += blockDim.x) {
        if (i < 20) s_pred[i] = g_w[i];
        else        s_w[i - 20] = g_w[i];
    }
    __syncthreads();

    // ---- per-lane B fragments (k-permutation pi(p)=2p / 2p-7 baked into
    // layers 2,3 to match the previous layer's C fragment layout).
    // Layer 1: A cols are (sx,sy,ah0,ah1) natively; cols 4..7 are zero.
    const unsigned B1_0 = tf32_of(s_w[gid * 4 + tig]);            // rc1_w[gid][tig]
    const unsigned B1_1 = 0u;                                     // k=tig+4 unused (A zero)
    const unsigned B2_0 = tf32_of(s_w[40 + gid * 8 + 2 * tig]);   // rc2_w[gid][2*tig]
    const unsigned B2_1 = tf32_of(s_w[40 + gid * 8 + 2 * tig + 1]);
    const unsigned B3_0 = (gid < 2) ? tf32_of(s_w[112 + gid * 8 + 2 * tig])     : 0u;
    const unsigned B3_1 = (gid < 2) ? tf32_of(s_w[112 + gid * 8 + 2 * tig + 1]) : 0u;
    // bias C-fragments (cols 2*tig, 2*tig+1; rows share columns)
    const float Cb1a = s_w[32 + 2 * tig],  Cb1b = s_w[32 + 2 * tig + 1];
    const float Cb2a = s_w[104 + 2 * tig], Cb2b = s_w[104 + 2 * tig + 1];
    const float Cb3a = (tig == 0) ? s_w[128] : 0.f;
    const float Cb3b = (tig == 0) ? s_w[129] : 0.f;

    const float Wf00 = s_pred[0], Wf01 = s_pred[1], Wf10 = s_pred[2], Wf11 = s_pred[3];
    const float Wh00 = s_pred[4], Wh01 = s_pred[5], Wh10 = s_pred[6], Wh11 = s_pred[7];

    // NO early return: warps are cooperative (MMA + syncwarp). OOB rows clamp.
    const int base = (blockIdx.x * blockDim.x + tid) * RPT;

    float sx[RPT], sy[RPT], ssx[RPT], ssy[RPT], err[RPT];
    float Cf0[RPT], Cf1[RPT], Ch0[RPT], Ch1[RPT];
    #pragma unroll
    for (int r = 0; r < RPT; ++r) {
        const int i = (base + r < B) ? base + r : B - 1;
        const float2 ssv = reinterpret_cast<const float2*>(s_star)[i];
        const float2 s0v = reinterpret_cast<const float2*>(s0)[i];
        ssx[r] = ssv.x; ssy[r] = ssv.y;
        sx[r] = s0v.x;  sy[r] = s0v.y;  err[r] = 0.f;
        Cf0[r] = fmaf(s_pred[8],  ssv.x, fmaf(s_pred[9],  ssv.y, s_pred[16]));
        Cf1[r] = fmaf(s_pred[10], ssv.x, fmaf(s_pred[11], ssv.y, s_pred[17]));
        Ch0[r] = fmaf(s_pred[12], ssv.x, fmaf(s_pred[13], ssv.y, s_pred[18]));
        Ch1[r] = fmaf(s_pred[14], ssv.x, fmaf(s_pred[15], ssv.y, s_pred[19]));
    }

    float* xw  = x_sm[wid];
    float* arw = ar_sm[wid];

    #pragma unroll 1
    for (int t = 0; t < 10; ++t) {
        // ---- scalar: pred nets + err terms (exact R10 math) + stage x rows
        #pragma unroll
        for (int r = 0; r < RPT; ++r) {
            const float ah0 = tanh_fast(fmaf(Wf00, sx[r], fmaf(Wf01, sy[r], Cf0[r])));
            const float ah1 = tanh_fast(fmaf(Wf10, sx[r], fmaf(Wf11, sy[r], Cf1[r])));
            const float ag0 = tanh_fast(fmaf(Wh00, sx[r], fmaf(Wh01, sy[r], Ch0[r])));
            const float ag1 = tanh_fast(fmaf(Wh10, sx[r], fmaf(Wh11, sy[r], Ch1[r])));
            const float d0 = ah0 - ag0, d1 = ah1 - ag1;
            float e = err[r];
            e += sqrt_fast(fmaf(d0, d0, d1 * d1));
            e += tanh_fast(ah0) + tanh_fast(ah1);
            e += sqrt_fast(fmaf(ah0, ah0, ah1 * ah1));
            err[r] = e;
            // row index inside warp: wrow = r*32 + lane (bijection on 0..95)
            float4 xv = make_float4(sx[r], sy[r], ah0, ah1);
            *reinterpret_cast<float4*>(xw + (r * 32 + lane) * 4) = xv;
        }
        __syncwarp();

        // ---- tensor-core rc chain, 6 tiles of 16 rows
        #pragma unroll
        for (int tt = 0; tt < NTILE; ++tt) {
            // A1: a0 = x[16*tt+gid][tig] at word 64*tt + lane (linear, no conflicts)
            const unsigned a0 = tf32_of(xw[64 * tt + lane]);
            const unsigned a1 = tf32_of(xw[64 * tt + 32 + lane]);
            float d0, d1, d2, d3;
            mma_tf32(d0, d1, d2, d3, a0, a1, 0u, 0u, B1_0, B1_1,
                     Cb1a, Cb1b, Cb1a, Cb1b);
            // tanh + relabel C->A (A2 = (c0, c2, c1, c3)) with pi baked into B2
            const unsigned p0 = tf32_of(tanh_fast(d0));
            const unsigned p1 = tf32_of(tanh_fast(d2));
            const unsigned p2 = tf32_of(tanh_fast(d1));
            const unsigned p3 = tf32_of(tanh_fast(d3));
            mma_tf32(d0, d1, d2, d3, p0, p1, p2, p3, B2_0, B2_1,
                     Cb2a, Cb2b, Cb2a, Cb2b);
            const unsigned q0 = tf32_of(tanh_fast(d0));
            const unsigned q1 = tf32_of(tanh_fast(d2));
            const unsigned q2 = tf32_of(tanh_fast(d1));
            const unsigned q3 = tf32_of(tanh_fast(d3));
            mma_tf32(d0, d1, d2, d3, q0, q1, q2, q3, B3_0, B3_1,
                     Cb3a, Cb3b, Cb3a, Cb3b);
            // ar for row 16*tt+gid in (d0,d1), row 16*tt+gid+8 in (d2,d3) — tig==0 lanes
            if (tig == 0) {
                *reinterpret_cast<float2*>(arw + (16 * tt + gid) * 2)     = make_float2(d0, d1);
                *reinterpret_cast<float2*>(arw + (16 * tt + gid + 8) * 2) = make_float2(d2, d3);
            }
        }
        __syncwarp();

        // ---- scalar: state update + tracking error
        #pragma unroll
        for (int r = 0; r < RPT; ++r) {
            const float2 ar = *reinterpret_cast<const float2*>(arw + (r * 32 + lane) * 2);
            sx[r] = fmaf(0.1f, ar.x, sx[r]);
            sy[r] = fmaf(0.1f, ar.y, sy[r]);
            const float dx = sx[r] - ssx[r], dy = sy[r] - ssy[r];
            err[r] += fmaf(dx, dx, dy * dy);
        }
    }

    #pragma unroll
    for (int r = 0; r < RPT; ++r)
        if (base + r < B) out[base + r] = err[r];
}

extern "C" void kernel_launch(void* const* d_in, const int* in_sizes, int n_in,
                              void* d_out, int out_size)
{
    const float* s_star = (const float*)d_in[0];
    const float* s0     = (const float*)d_in[1];
    const float* fc1_w  = (const float*)d_in[2];
    const float* fc1_b  = (const float*)d_in[3];
    const float* fc2_w  = (const float*)d_in[4];
    const float* fc2_b  = (const float*)d_in[5];
    const float* rc1_w  = (const float*)d_in[6];
    const float* rc1_b  = (const float*)d_in[7];
    const float* rc2_w  = (const float*)d_in[8];
    const float* rc2_b  = (const float*)d_in[9];
    const float* rc3_w  = (const float*)d_in[10];
    const float* rc3_b  = (const float*)d_in[11];
    const float* hf1_w  = (const float*)d_in[12];
    const float* hf1_b  = (const float*)d_in[13];
    const float* hf2_w  = (const float*)d_in[14];
    const float* hf2_b  = (const float*)d_in[15];
    float* out = (float*)d_out;

    const int B = out_size;

    prep_kernel<<<1, 1>>>(fc1_w, fc1_b, fc2_w, fc2_b,
                          rc1_w, rc1_b, rc2_w, rc2_b, rc3_w, rc3_b,
                          hf1_w, hf1_b, hf2_w, hf2_b);

    const int threads = 128;
    const int rows_per_block = threads * RPT;
    const int blocks = (B + rows_per_block - 1) / rows_per_block;
    rollout_kernel<<<blocks, threads>>>(s_star, s0, out, B);
}